// round 11
// baseline (speedup 1.0000x reference)
#include <cuda_runtime.h>
#include <cuda_bf16.h>
#include <math.h>
#include <stdint.h>

// ----------------------------------------------------------------------------
// k' = k(0.8+0.28g) + 0.52 g v ; v' = 0.8 v + 0.2 u_t ; g = g(k^2+u^2).
// Out: tanh(k_final).   (64-pt GL quadrature folded into host-built table.)
//
// 1) Contraction: only LAST W=512 steps from (0,0) matter (validated R3/R4).
// 2) Host-built linearized table g ~ a_i + b_i*s (2048 entries over [0,24]),
//    passed by value as 16KB kernel param; const-path misses serialize per-SM
//    (R9 evidence), so Kernel A spreads param->global over 256 tiny blocks and
//    Kernel B stages global->SMEM via deep-MLP LDG (validated R10).
// 3) Picard + affine warp scan (32 thr x 16 steps). NSWEEP=6: R8==R12-sweep
//    bit-identity bounds the per-sweep contraction factor <=0.145, so sweep-6
//    residual <=5e-6 (under the 1.6e-5 table floor).
// ----------------------------------------------------------------------------

#define GLN 64
#define NTAB 2048
#define S_MAX 24.0f
#define INV_DS ((float)NTAB / S_MAX)
#define W 512
#define TPB 512
#define CHUNK 16
#define NSWEEP 6

struct TabParam { float2 e[NTAB]; };   // 16384 bytes, by value

__device__ float2 g_tab_dev[NTAB];     // global staging of the table

// ---------------------------------------------------------------------------
// Kernel A: param(const bank) -> global, one 64B line per block, many SMs.
// ---------------------------------------------------------------------------
__global__ void __launch_bounds__(8, 1)
copy_tab_kernel(TabParam tp) {
    int i = blockIdx.x * 8 + threadIdx.x;   // 8 float2 = 64 B per block
    g_tab_dev[i] = tp.e[i];
}

// ---------------------------------------------------------------------------
// Warp inclusive affine scan; last level computes B only (A unused after).
// ---------------------------------------------------------------------------
__device__ __forceinline__ void warp_scan_affine_Bout(float& A, float& B, int lane) {
    #pragma unroll
    for (int off = 1; off < 16; off <<= 1) {
        float Ag = __shfl_up_sync(0xFFFFFFFFu, A, off);
        float Bg = __shfl_up_sync(0xFFFFFFFFu, B, off);
        if (lane >= off) { B = fmaf(A, Bg, B); A *= Ag; }
    }
    // final level: only B needed downstream
    float Bg = __shfl_up_sync(0xFFFFFFFFu, B, 16);
    if (lane >= 16) B = fmaf(A, Bg, B);
}

// ---------------------------------------------------------------------------
// Kernel B: stage table global->SMEM (LDG, 16 warps), warp 0 computes.
// ---------------------------------------------------------------------------
__global__ void __launch_bounds__(TPB, 1)
run_kernel(const float* __restrict__ u, float* __restrict__ out, int n) {
    __shared__ float2 tab[NTAB];   // 16 KB
    const int tid  = threadIdx.x;
    const int lane = tid & 31;

    // warp 0 issues its u loads FIRST so DRAM latency overlaps table staging
    float su2[CHUNK], cj[CHUNK], k[CHUNK];
    if (tid < 32) {
        const int base = n - W + lane * CHUNK;
        #pragma unroll
        for (int j = 0; j < CHUNK; ++j) {
            int gi = base + j;
            float x = (gi >= 0) ? u[gi] : 0.0f;   // zero-pad front (exact)
            cj[j] = x;                             // stash u temporarily
            su2[j] = x * x;
            k[j] = 0.0f;
        }
    }

    // all 16 warps stage the table from L2-hot global (deep-MLP LDG path)
    {
        const float4* src = (const float4*)g_tab_dev;
        float4* dst = (float4*)tab;
        dst[tid]       = src[tid];
        dst[tid + 512] = src[tid + 512];
    }
    __syncthreads();
    if (tid >= 32) return;

    // ---- v scan: v_t = 0.8 v_{t-1} + 0.2 u_t, v_0 = 0; cj = 0.52*v_{t-1} ---
    {
        float B = 0.0f;
        float Bp[CHUNK];                       // inclusive B prefix (A = 0.8^j)
        #pragma unroll
        for (int j = 0; j < CHUNK; ++j) {
            B = fmaf(0.8f, B, 0.2f * cj[j]);
            Bp[j] = B;
        }
        float As = 0.0281474976710656f;        // 0.8^16
        float Bs = B;
        warp_scan_affine_Bout(As, Bs, lane);
        float vstart = __shfl_up_sync(0xFFFFFFFFu, Bs, 1);
        if (lane == 0) vstart = 0.0f;
        float Aj = 1.0f;
        cj[0] = 0.52f * vstart;
        #pragma unroll
        for (int j = 1; j < CHUNK; ++j) {
            Aj *= 0.8f;                        // 0.8^j
            cj[j] = 0.52f * fmaf(Aj, vstart, Bp[j - 1]);
        }
    }

    unsigned sbase = (unsigned)__cvta_generic_to_shared(tab);
    const unsigned OFFC = sbase - 0x58000000u;   // sbase - 8*0x4B000000 mod 2^32
    const float MAGIC = 8388608.0f;              // 2^23 (round-to-nearest)
    const float TMAX  = MAGIC + (float)(NTAB - 1);

    float klast = 0.0f;

    #pragma unroll 1
    for (int sw = 0; sw < NSWEEP; ++sw) {
        float knb = __shfl_up_sync(0xFFFFFFFFu, klast, 1);
        if (lane == 0) knb = 0.0f;

        // fused: lookup + affine coeff + local inclusive compose
        float Al[CHUNK], Bl[CHUNK];
        float A = 1.0f, B = 0.0f;
        #pragma unroll
        for (int j = 0; j < CHUNK; ++j) {
            float kp = (j == 0) ? knb : k[j - 1];
            float s  = fmaf(kp, kp, su2[j]);
            float tt = fminf(fmaf(s, INV_DS, MAGIC), TMAX);
            unsigned addr = __float_as_uint(tt) * 8u + OFFC;
            float a_, b_;
            asm("ld.shared.v2.f32 {%0,%1},[%2];"
                : "=f"(a_), "=f"(b_) : "r"(addr));
            float g  = fmaf(b_, s, a_);
            float at = fmaf(0.28f, g, 0.8f);
            float bt = g * cj[j];
            B = fmaf(at, B, bt);
            A = at * A;
            Al[j] = A; Bl[j] = B;
        }

        // warp scan (B-only final level) + exclusive start (k_0 = 0)
        float As = A, Bs = B;
        warp_scan_affine_Bout(As, Bs, lane);
        float kstart = __shfl_up_sync(0xFFFFFFFFu, Bs, 1);
        if (lane == 0) kstart = 0.0f;

        // rebuild trajectory (independent FMAs)
        #pragma unroll
        for (int j = 0; j < CHUNK; ++j)
            k[j] = fmaf(Al[j], kstart, Bl[j]);
        klast = k[CHUNK - 1];
    }

    if (lane == 31) *out = tanhf(k[CHUNK - 1]);
}

// ---------------------------------------------------------------------------
// Host: Gauss-Legendre n=64 + table build (double precision, input-indep).
// ---------------------------------------------------------------------------
static void host_leggauss64(double* x, double* w) {
    const int n = GLN;
    const double PI = 3.14159265358979323846;
    for (int i = 0; i < n; ++i) {
        double xi = cos(PI * (i + 0.75) / (n + 0.5));
        double p0 = 1.0, p1 = 0.0, pp = 1.0;
        for (int it = 0; it < 100; ++it) {
            p0 = 1.0; p1 = 0.0;
            for (int j = 1; j <= n; ++j) {
                double p2 = p1; p1 = p0;
                p0 = ((2.0 * j - 1.0) * xi * p1 - (j - 1.0) * p2) / j;
            }
            pp = n * (xi * p0 - p1) / (xi * xi - 1.0);
            double dx = p0 / pp;
            xi -= dx;
            if (fabs(dx) < 1e-15) break;
        }
        p0 = 1.0; p1 = 0.0;
        for (int j = 1; j <= n; ++j) {
            double p2 = p1; p1 = p0;
            p0 = ((2.0 * j - 1.0) * xi * p1 - (j - 1.0) * p2) / j;
        }
        pp = n * (xi * p0 - p1) / (xi * xi - 1.0);
        x[i] = xi;
        w[i] = 2.0 / ((1.0 - xi * xi) * pp * pp);
    }
}

static double host_g(double s, const double* X, const double* EW) {
    double d = sqrt(s);
    double acc = 0.0;
    for (int q = 0; q < GLN; ++q) {
        double th = tanh(d * X[q]);
        acc += EW[q] * (1.0 - th * th);
    }
    return acc * 0.15915494309189535;   // 1/(2*pi)
}

static void host_build_table(TabParam* tp) {
    double x[GLN], wq[GLN], X[GLN], EW[GLN];
    host_leggauss64(x, wq);
    for (int q = 0; q < GLN; ++q) {
        X[q]  = x[q] * 5.0;
        EW[q] = wq[q] * 5.0 * exp(-X[q] * X[q] * 0.5);
    }
    const double ds = (double)S_MAX / (double)NTAB;
    for (int i = 0; i < NTAB; ++i) {
        double s  = i * ds;
        double h  = 0.5 * ds;
        double sl = (s - h > 0.0) ? (s - h) : 0.0;
        double sh = s + h;
        double g0 = host_g(s,  X, EW);
        double gm = host_g(sl, X, EW);
        double gp = host_g(sh, X, EW);
        double bb = (gp - gm) / (sh - sl);
        tp->e[i].x = (float)(g0 - bb * s);
        tp->e[i].y = (float)bb;
    }
}

// ---------------------------------------------------------------------------
extern "C" void kernel_launch(void* const* d_in, const int* in_sizes, int n_in,
                              void* d_out, int out_size) {
    (void)n_in; (void)out_size;
    const float* u = (const float*)d_in[0];
    float* out = (float*)d_out;
    int n = in_sizes[0];

    static TabParam tp;
    host_build_table(&tp);   // deterministic, host-side, input-independent

    copy_tab_kernel<<<NTAB / 8, 8>>>(tp);     // param -> global, spread wide
    run_kernel<<<1, TPB>>>(u, out, n);        // global(L2) -> SMEM, compute
}

// round 12
// speedup vs baseline: 1.0895x; 1.0895x over previous
#include <cuda_runtime.h>
#include <cuda_bf16.h>
#include <math.h>
#include <stdint.h>

// ----------------------------------------------------------------------------
// k' = k(0.8+0.28g) + 0.52 g v ; v' = 0.8 v + 0.2 u_t ; g = g(k^2+u^2).
// Out: tanh(k_final).   (64-pt GL quadrature folded into host-built table.)
//
// 1) Contraction: only LAST W steps from (0,0) matter. W=256 (rho^256 <=
//    3e-5 even worst-case; realistic e-24). Validated at W=512/2048 (R3/R4).
// 2) Host-built linearized table g ~ a_i + b_i*s (1024 entries over [0,24]),
//    by-value kernel param -> spread-wide copy kernel (const-path misses
//    serialize per-SM, R9) -> global -> SMEM via deep-MLP LDG (R10).
// 3) Picard + affine warp scan, 6 sweeps (R8: converged; R11: sweeps are
//    ~0.1us each). R12: ONE-WARP kernel — sweeps were only ~1.2us of 7.1;
//    the 512-thread staging/sync/ramp prologue was the floor. Single warp
//    stages 8KB itself (LDG L2 path ~0.5us), __syncwarp only, u loads
//    issued first to overlap DRAM latency.
// ----------------------------------------------------------------------------

#define GLN 64
#define NTAB 1024
#define S_MAX 24.0f
#define INV_DS ((float)NTAB / S_MAX)
#define W 256
#define TPB 32
#define CHUNK 8           // W / TPB
#define NSWEEP 6

struct TabParam { float2 e[NTAB]; };   // 8192 bytes, by value

__device__ float2 g_tab_dev[NTAB];     // global staging of the table

// ---------------------------------------------------------------------------
// Kernel A: param(const bank) -> global, one 64B line per block, many SMs.
// ---------------------------------------------------------------------------
__global__ void __launch_bounds__(8, 1)
copy_tab_kernel(TabParam tp) {
    int i = blockIdx.x * 8 + threadIdx.x;   // 8 float2 = 64 B per block
    g_tab_dev[i] = tp.e[i];
}

// ---------------------------------------------------------------------------
// Warp inclusive affine scan; last level computes B only (A unused after).
// ---------------------------------------------------------------------------
__device__ __forceinline__ void warp_scan_affine_Bout(float& A, float& B, int lane) {
    #pragma unroll
    for (int off = 1; off < 16; off <<= 1) {
        float Ag = __shfl_up_sync(0xFFFFFFFFu, A, off);
        float Bg = __shfl_up_sync(0xFFFFFFFFu, B, off);
        if (lane >= off) { B = fmaf(A, Bg, B); A *= Ag; }
    }
    float Bg = __shfl_up_sync(0xFFFFFFFFu, B, 16);
    if (lane >= 16) B = fmaf(A, Bg, B);
}

// ---------------------------------------------------------------------------
// Kernel B: ONE WARP. u loads first, table global->SMEM, v scan, 6 sweeps.
// ---------------------------------------------------------------------------
__global__ void __launch_bounds__(TPB, 1)
run_kernel(const float* __restrict__ u, float* __restrict__ out, int n) {
    __shared__ float2 tab[NTAB];   // 8 KB
    const int lane = threadIdx.x;

    // u window first (overlap DRAM latency with table staging below)
    float su2[CHUNK], cj[CHUNK], k[CHUNK];
    const int base = n - W + lane * CHUNK;
    if (base >= 0) {                         // fast path (n >= W, aligned)
        float4 a = *(const float4*)(u + base);
        float4 b = *(const float4*)(u + base + 4);
        cj[0]=a.x; cj[1]=a.y; cj[2]=a.z; cj[3]=a.w;
        cj[4]=b.x; cj[5]=b.y; cj[6]=b.z; cj[7]=b.w;
    } else {
        #pragma unroll
        for (int j = 0; j < CHUNK; ++j) {
            int gi = base + j;
            cj[j] = (gi >= 0) ? u[gi] : 0.0f;   // zero-pad front (exact)
        }
    }
    #pragma unroll
    for (int j = 0; j < CHUNK; ++j) { su2[j] = cj[j] * cj[j]; k[j] = 0.0f; }

    // table: global (L2-hot from kernel A) -> SMEM, 16 float4 per thread
    {
        const float4* src = (const float4*)g_tab_dev;
        float4* dst = (float4*)tab;
        #pragma unroll
        for (int j = 0; j < NTAB / 2 / TPB; ++j)     // 512 float4 total
            dst[lane + j * TPB] = src[lane + j * TPB];
    }

    // ---- v scan: v_t = 0.8 v_{t-1} + 0.2 u_t, v_0 = 0; cj = 0.52*v_{t-1} ---
    {
        float B = 0.0f;
        float Bp[CHUNK];
        #pragma unroll
        for (int j = 0; j < CHUNK; ++j) {
            B = fmaf(0.8f, B, 0.2f * cj[j]);
            Bp[j] = B;
        }
        float As = 0.16777216f;                // 0.8^8
        float Bs = B;
        warp_scan_affine_Bout(As, Bs, lane);
        float vstart = __shfl_up_sync(0xFFFFFFFFu, Bs, 1);
        if (lane == 0) vstart = 0.0f;
        float Aj = 1.0f;
        cj[0] = 0.52f * vstart;
        #pragma unroll
        for (int j = 1; j < CHUNK; ++j) {
            Aj *= 0.8f;
            cj[j] = 0.52f * fmaf(Aj, vstart, Bp[j - 1]);
        }
    }

    __syncwarp();   // table STS visible across lanes

    unsigned sbase = (unsigned)__cvta_generic_to_shared(tab);
    const unsigned OFFC = sbase - 0x58000000u;   // sbase - 8*0x4B000000 mod 2^32
    const float MAGIC = 8388608.0f;              // 2^23 (round-to-nearest)
    const float TMAX  = MAGIC + (float)(NTAB - 1);

    float klast = 0.0f;

    #pragma unroll 1
    for (int sw = 0; sw < NSWEEP; ++sw) {
        float knb = __shfl_up_sync(0xFFFFFFFFu, klast, 1);
        if (lane == 0) knb = 0.0f;

        float Al[CHUNK], Bl[CHUNK];
        float A = 1.0f, B = 0.0f;
        #pragma unroll
        for (int j = 0; j < CHUNK; ++j) {
            float kp = (j == 0) ? knb : k[j - 1];
            float s  = fmaf(kp, kp, su2[j]);
            float tt = fminf(fmaf(s, INV_DS, MAGIC), TMAX);
            unsigned addr = __float_as_uint(tt) * 8u + OFFC;
            float a_, b_;
            asm("ld.shared.v2.f32 {%0,%1},[%2];"
                : "=f"(a_), "=f"(b_) : "r"(addr));
            float g  = fmaf(b_, s, a_);
            float at = fmaf(0.28f, g, 0.8f);
            float bt = g * cj[j];
            B = fmaf(at, B, bt);
            A = at * A;
            Al[j] = A; Bl[j] = B;
        }

        float As = A, Bs = B;
        warp_scan_affine_Bout(As, Bs, lane);
        float kstart = __shfl_up_sync(0xFFFFFFFFu, Bs, 1);
        if (lane == 0) kstart = 0.0f;

        #pragma unroll
        for (int j = 0; j < CHUNK; ++j)
            k[j] = fmaf(Al[j], kstart, Bl[j]);
        klast = k[CHUNK - 1];
    }

    if (lane == 31) *out = tanhf(k[CHUNK - 1]);
}

// ---------------------------------------------------------------------------
// Host: Gauss-Legendre n=64 + table build (double precision, input-indep).
// ---------------------------------------------------------------------------
static void host_leggauss64(double* x, double* w) {
    const int n = GLN;
    const double PI = 3.14159265358979323846;
    for (int i = 0; i < n; ++i) {
        double xi = cos(PI * (i + 0.75) / (n + 0.5));
        double p0 = 1.0, p1 = 0.0, pp = 1.0;
        for (int it = 0; it < 100; ++it) {
            p0 = 1.0; p1 = 0.0;
            for (int j = 1; j <= n; ++j) {
                double p2 = p1; p1 = p0;
                p0 = ((2.0 * j - 1.0) * xi * p1 - (j - 1.0) * p2) / j;
            }
            pp = n * (xi * p0 - p1) / (xi * xi - 1.0);
            double dx = p0 / pp;
            xi -= dx;
            if (fabs(dx) < 1e-15) break;
        }
        p0 = 1.0; p1 = 0.0;
        for (int j = 1; j <= n; ++j) {
            double p2 = p1; p1 = p0;
            p0 = ((2.0 * j - 1.0) * xi * p1 - (j - 1.0) * p2) / j;
        }
        pp = n * (xi * p0 - p1) / (xi * xi - 1.0);
        x[i] = xi;
        w[i] = 2.0 / ((1.0 - xi * xi) * pp * pp);
    }
}

static double host_g(double s, const double* X, const double* EW) {
    double d = sqrt(s);
    double acc = 0.0;
    for (int q = 0; q < GLN; ++q) {
        double th = tanh(d * X[q]);
        acc += EW[q] * (1.0 - th * th);
    }
    return acc * 0.15915494309189535;   // 1/(2*pi)
}

static void host_build_table(TabParam* tp) {
    double x[GLN], wq[GLN], X[GLN], EW[GLN];
    host_leggauss64(x, wq);
    for (int q = 0; q < GLN; ++q) {
        X[q]  = x[q] * 5.0;
        EW[q] = wq[q] * 5.0 * exp(-X[q] * X[q] * 0.5);
    }
    const double ds = (double)S_MAX / (double)NTAB;
    for (int i = 0; i < NTAB; ++i) {
        double s  = i * ds;
        double h  = 0.5 * ds;
        double sl = (s - h > 0.0) ? (s - h) : 0.0;
        double sh = s + h;
        double g0 = host_g(s,  X, EW);
        double gm = host_g(sl, X, EW);
        double gp = host_g(sh, X, EW);
        double bb = (gp - gm) / (sh - sl);
        tp->e[i].x = (float)(g0 - bb * s);
        tp->e[i].y = (float)bb;
    }
}

// ---------------------------------------------------------------------------
extern "C" void kernel_launch(void* const* d_in, const int* in_sizes, int n_in,
                              void* d_out, int out_size) {
    (void)n_in; (void)out_size;
    const float* u = (const float*)d_in[0];
    float* out = (float*)d_out;
    int n = in_sizes[0];

    static TabParam tp;
    host_build_table(&tp);   // deterministic, host-side, input-independent

    copy_tab_kernel<<<NTAB / 8, 8>>>(tp);     // param -> global, spread wide
    run_kernel<<<1, TPB>>>(u, out, n);        // global(L2) -> SMEM, 1 warp
}

// round 13
// speedup vs baseline: 1.0938x; 1.0039x over previous
#include <cuda_runtime.h>
#include <cuda_bf16.h>
#include <math.h>
#include <stdint.h>

// ----------------------------------------------------------------------------
// k' = k(0.8+0.28g) + 0.52 g v ; v' = 0.8 v + 0.2 u_t ; g = g(k^2+u^2).
// Out: tanh(k_final).   (64-pt GL quadrature folded into host-built table.)
//
// 1) Contraction: only LAST W=256 steps from (0,0) matter (validated chain
//    R3/R4/R12; W=256 residual <= 3e-5 worst-case, e-24 realistic).
// 2) Host-built linearized table g ~ a_i + b_i*s (1024 entries over [0,24]),
//    passed by value as an 8KB kernel parameter. Const-path misses serialize
//    PER-SM (R9), so 128 copier BLOCKS (spread across SMs) each move one 64B
//    line param->global; compute reads it back via the deep-MLP LDG/L2 path.
// 3) SINGLE KERNEL (R13): copiers + compute fused. Per-block done-flags in
//    __device__ globals: first call block 0 waits for the copiers; on graph
//    replays flags are already set and the table already holds identical
//    bytes (benign same-value race), so block 0 proceeds with zero wait.
//    Same work every call -> deterministic output.
// 4) Picard + affine warp scan, one warp, 6 sweeps (validated R7-R12).
// ----------------------------------------------------------------------------

#define GLN 64
#define NTAB 1024
#define S_MAX 24.0f
#define INV_DS ((float)NTAB / S_MAX)
#define W 256
#define TPB 32
#define CHUNK 8           // W / TPB
#define NSWEEP 6
#define NCOPY 128         // copier blocks; 8 float2 = 64B each

struct TabParam { float2 e[NTAB]; };   // 8192 bytes, by value

__device__ float2 g_tab_dev[NTAB];       // global staging of the table
__device__ volatile int g_flags[NCOPY];  // zero at module load only

// ---------------------------------------------------------------------------
// Warp inclusive affine scan; last level computes B only (A unused after).
// ---------------------------------------------------------------------------
__device__ __forceinline__ void warp_scan_affine_Bout(float& A, float& B, int lane) {
    #pragma unroll
    for (int off = 1; off < 16; off <<= 1) {
        float Ag = __shfl_up_sync(0xFFFFFFFFu, A, off);
        float Bg = __shfl_up_sync(0xFFFFFFFFu, B, off);
        if (lane >= off) { B = fmaf(A, Bg, B); A *= Ag; }
    }
    float Bg = __shfl_up_sync(0xFFFFFFFFu, B, 16);
    if (lane >= 16) B = fmaf(A, Bg, B);
}

// ---------------------------------------------------------------------------
// ONE kernel: blocks 1..NCOPY copy the param table; block 0 computes.
// ---------------------------------------------------------------------------
__global__ void __launch_bounds__(TPB, 1)
run_kernel(TabParam tp, const float* __restrict__ u,
           float* __restrict__ out, int n) {
    const int lane = threadIdx.x;

    if (blockIdx.x > 0) {
        // copier block: one 64B line, param(const) -> global, then flag
        int b = blockIdx.x - 1;
        if (lane < 8)
            g_tab_dev[b * 8 + lane] = tp.e[b * 8 + lane];
        __threadfence();
        __syncwarp();
        if (lane == 0) g_flags[b] = 1;
        return;
    }

    // ---- block 0: compute ---------------------------------------------------
    __shared__ float2 tab[NTAB];   // 8 KB

    // u window first (overlap DRAM latency with copier blocks / v scan)
    float su2[CHUNK], cj[CHUNK], k[CHUNK];
    const int base = n - W + lane * CHUNK;
    if (base >= 0) {                         // fast path (n >= W, aligned)
        float4 a = *(const float4*)(u + base);
        float4 b = *(const float4*)(u + base + 4);
        cj[0]=a.x; cj[1]=a.y; cj[2]=a.z; cj[3]=a.w;
        cj[4]=b.x; cj[5]=b.y; cj[6]=b.z; cj[7]=b.w;
    } else {
        #pragma unroll
        for (int j = 0; j < CHUNK; ++j) {
            int gi = base + j;
            cj[j] = (gi >= 0) ? u[gi] : 0.0f;   // zero-pad front (exact)
        }
    }
    #pragma unroll
    for (int j = 0; j < CHUNK; ++j) { su2[j] = cj[j] * cj[j]; k[j] = 0.0f; }

    // ---- v scan: v_t = 0.8 v_{t-1} + 0.2 u_t, v_0 = 0; cj = 0.52*v_{t-1} ---
    {
        float B = 0.0f;
        float Bp[CHUNK];
        #pragma unroll
        for (int j = 0; j < CHUNK; ++j) {
            B = fmaf(0.8f, B, 0.2f * cj[j]);
            Bp[j] = B;
        }
        float As = 0.16777216f;                // 0.8^8
        float Bs = B;
        warp_scan_affine_Bout(As, Bs, lane);
        float vstart = __shfl_up_sync(0xFFFFFFFFu, Bs, 1);
        if (lane == 0) vstart = 0.0f;
        float Aj = 1.0f;
        cj[0] = 0.52f * vstart;
        #pragma unroll
        for (int j = 1; j < CHUNK; ++j) {
            Aj *= 0.8f;
            cj[j] = 0.52f * fmaf(Aj, vstart, Bp[j - 1]);
        }
    }

    // ---- wait for copiers (zero wait on replays: flags persist) ------------
    {
        int ok;
        do {
            int f = g_flags[lane] & g_flags[lane + 32]
                  & g_flags[lane + 64] & g_flags[lane + 96];
            ok = __all_sync(0xFFFFFFFFu, f);
        } while (!ok);
        __threadfence();
    }

    // table: global (L2-hot) -> SMEM, 16 float4 per thread
    {
        const float4* src = (const float4*)g_tab_dev;
        float4* dst = (float4*)tab;
        #pragma unroll
        for (int j = 0; j < NTAB / 2 / TPB; ++j)     // 512 float4 total
            dst[lane + j * TPB] = src[lane + j * TPB];
    }
    __syncwarp();   // table STS visible across lanes

    unsigned sbase = (unsigned)__cvta_generic_to_shared(tab);
    const unsigned OFFC = sbase - 0x58000000u;   // sbase - 8*0x4B000000 mod 2^32
    const float MAGIC = 8388608.0f;              // 2^23 (round-to-nearest)
    const float TMAX  = MAGIC + (float)(NTAB - 1);

    float klast = 0.0f;

    #pragma unroll 1
    for (int sw = 0; sw < NSWEEP; ++sw) {
        float knb = __shfl_up_sync(0xFFFFFFFFu, klast, 1);
        if (lane == 0) knb = 0.0f;

        float Al[CHUNK], Bl[CHUNK];
        float A = 1.0f, B = 0.0f;
        #pragma unroll
        for (int j = 0; j < CHUNK; ++j) {
            float kp = (j == 0) ? knb : k[j - 1];
            float s  = fmaf(kp, kp, su2[j]);
            float tt = fminf(fmaf(s, INV_DS, MAGIC), TMAX);
            unsigned addr = __float_as_uint(tt) * 8u + OFFC;
            float a_, b_;
            asm("ld.shared.v2.f32 {%0,%1},[%2];"
                : "=f"(a_), "=f"(b_) : "r"(addr));
            float g  = fmaf(b_, s, a_);
            float at = fmaf(0.28f, g, 0.8f);
            float bt = g * cj[j];
            B = fmaf(at, B, bt);
            A = at * A;
            Al[j] = A; Bl[j] = B;
        }

        float As = A, Bs = B;
        warp_scan_affine_Bout(As, Bs, lane);
        float kstart = __shfl_up_sync(0xFFFFFFFFu, Bs, 1);
        if (lane == 0) kstart = 0.0f;

        #pragma unroll
        for (int j = 0; j < CHUNK; ++j)
            k[j] = fmaf(Al[j], kstart, Bl[j]);
        klast = k[CHUNK - 1];
    }

    if (lane == 31) *out = tanhf(k[CHUNK - 1]);
}

// ---------------------------------------------------------------------------
// Host: Gauss-Legendre n=64 + table build (double precision, input-indep).
// ---------------------------------------------------------------------------
static void host_leggauss64(double* x, double* w) {
    const int n = GLN;
    const double PI = 3.14159265358979323846;
    for (int i = 0; i < n; ++i) {
        double xi = cos(PI * (i + 0.75) / (n + 0.5));
        double p0 = 1.0, p1 = 0.0, pp = 1.0;
        for (int it = 0; it < 100; ++it) {
            p0 = 1.0; p1 = 0.0;
            for (int j = 1; j <= n; ++j) {
                double p2 = p1; p1 = p0;
                p0 = ((2.0 * j - 1.0) * xi * p1 - (j - 1.0) * p2) / j;
            }
            pp = n * (xi * p0 - p1) / (xi * xi - 1.0);
            double dx = p0 / pp;
            xi -= dx;
            if (fabs(dx) < 1e-15) break;
        }
        p0 = 1.0; p1 = 0.0;
        for (int j = 1; j <= n; ++j) {
            double p2 = p1; p1 = p0;
            p0 = ((2.0 * j - 1.0) * xi * p1 - (j - 1.0) * p2) / j;
        }
        pp = n * (xi * p0 - p1) / (xi * xi - 1.0);
        x[i] = xi;
        w[i] = 2.0 / ((1.0 - xi * xi) * pp * pp);
    }
}

static double host_g(double s, const double* X, const double* EW) {
    double d = sqrt(s);
    double acc = 0.0;
    for (int q = 0; q < GLN; ++q) {
        double th = tanh(d * X[q]);
        acc += EW[q] * (1.0 - th * th);
    }
    return acc * 0.15915494309189535;   // 1/(2*pi)
}

static void host_build_table(TabParam* tp) {
    double x[GLN], wq[GLN], X[GLN], EW[GLN];
    host_leggauss64(x, wq);
    for (int q = 0; q < GLN; ++q) {
        X[q]  = x[q] * 5.0;
        EW[q] = wq[q] * 5.0 * exp(-X[q] * X[q] * 0.5);
    }
    const double ds = (double)S_MAX / (double)NTAB;
    for (int i = 0; i < NTAB; ++i) {
        double s  = i * ds;
        double h  = 0.5 * ds;
        double sl = (s - h > 0.0) ? (s - h) : 0.0;
        double sh = s + h;
        double g0 = host_g(s,  X, EW);
        double gm = host_g(sl, X, EW);
        double gp = host_g(sh, X, EW);
        double bb = (gp - gm) / (sh - sl);
        tp->e[i].x = (float)(g0 - bb * s);
        tp->e[i].y = (float)bb;
    }
}

// ---------------------------------------------------------------------------
extern "C" void kernel_launch(void* const* d_in, const int* in_sizes, int n_in,
                              void* d_out, int out_size) {
    (void)n_in; (void)out_size;
    const float* u = (const float*)d_in[0];
    float* out = (float*)d_out;
    int n = in_sizes[0];

    static TabParam tp;
    host_build_table(&tp);   // deterministic, host-side, input-independent

    run_kernel<<<NCOPY + 1, TPB>>>(tp, u, out, n);   // single graph node
}

// round 14
// speedup vs baseline: 1.1570x; 1.0579x over previous
#include <cuda_runtime.h>
#include <cuda_bf16.h>
#include <math.h>
#include <stdint.h>

// ----------------------------------------------------------------------------
// k' = k(0.8+0.28g) + 0.52 g v ; v' = 0.8 v + 0.2 u_t ; g = g(k^2+u^2).
// Out: tanh(k_final).   (64-pt GL quadrature folded into host-built table.)
//
// Error budget (measured/calibrated R3-R13): base 1.3e-5; table term 4x per
// halving (1.2e-5 @NTAB=1024); Picard per-sweep factor ~0.14; truncation
// rho^W with rho<=0.92. This round spends margin: W=128, NSWEEP=5, NTAB=512
// -> predicted total ~1e-4, 10x under the 1e-3 threshold.
//
// Structure (validated): single fused kernel; 64 copier blocks move the 4KB
// by-value param table to global (const-path misses serialize PER-SM, R9);
// block 0 computes: u loads first, v affine warp scan, then Picard + affine
// warp scan on one warp. Done-flags persist across graph replays (benign
// same-value overwrite) -> zero wait after first call.
// ----------------------------------------------------------------------------

#define GLN 64
#define NTAB 512
#define S_MAX 24.0f
#define INV_DS ((float)NTAB / S_MAX)
#define W 128
#define TPB 32
#define CHUNK 4           // W / TPB
#define NSWEEP 5
#define NCOPY 64          // copier blocks; 8 float2 = 64B each

struct TabParam { float2 e[NTAB]; };   // 4096 bytes, by value

__device__ float2 g_tab_dev[NTAB];       // global staging of the table
__device__ volatile int g_flags[NCOPY];  // zero at module load only

// ---------------------------------------------------------------------------
// Warp inclusive affine scan; last level computes B only (A unused after).
// ---------------------------------------------------------------------------
__device__ __forceinline__ void warp_scan_affine_Bout(float& A, float& B, int lane) {
    #pragma unroll
    for (int off = 1; off < 16; off <<= 1) {
        float Ag = __shfl_up_sync(0xFFFFFFFFu, A, off);
        float Bg = __shfl_up_sync(0xFFFFFFFFu, B, off);
        if (lane >= off) { B = fmaf(A, Bg, B); A *= Ag; }
    }
    float Bg = __shfl_up_sync(0xFFFFFFFFu, B, 16);
    if (lane >= 16) B = fmaf(A, Bg, B);
}

// ---------------------------------------------------------------------------
// ONE kernel: blocks 1..NCOPY copy the param table; block 0 computes.
// ---------------------------------------------------------------------------
__global__ void __launch_bounds__(TPB, 1)
run_kernel(TabParam tp, const float* __restrict__ u,
           float* __restrict__ out, int n) {
    const int lane = threadIdx.x;

    if (blockIdx.x > 0) {
        int b = blockIdx.x - 1;
        if (lane < 8)
            g_tab_dev[b * 8 + lane] = tp.e[b * 8 + lane];
        __threadfence();
        __syncwarp();
        if (lane == 0) g_flags[b] = 1;
        return;
    }

    // ---- block 0: compute ---------------------------------------------------
    __shared__ float2 tab[NTAB];   // 4 KB

    // u window first (overlap DRAM latency with everything below)
    float su2[CHUNK], cj[CHUNK], k[CHUNK];
    const int base = n - W + lane * CHUNK;
    if (base >= 0) {                         // fast path (n >= W, aligned)
        float4 a = *(const float4*)(u + base);
        cj[0]=a.x; cj[1]=a.y; cj[2]=a.z; cj[3]=a.w;
    } else {
        #pragma unroll
        for (int j = 0; j < CHUNK; ++j) {
            int gi = base + j;
            cj[j] = (gi >= 0) ? u[gi] : 0.0f;   // zero-pad front (exact)
        }
    }
    #pragma unroll
    for (int j = 0; j < CHUNK; ++j) { su2[j] = cj[j] * cj[j]; k[j] = 0.0f; }

    // ---- v scan: v_t = 0.8 v_{t-1} + 0.2 u_t, v_0 = 0; cj = 0.52*v_{t-1} ---
    {
        float B = 0.0f;
        float Bp[CHUNK];
        #pragma unroll
        for (int j = 0; j < CHUNK; ++j) {
            B = fmaf(0.8f, B, 0.2f * cj[j]);
            Bp[j] = B;
        }
        float As = 0.40960000f;                // 0.8^4
        float Bs = B;
        warp_scan_affine_Bout(As, Bs, lane);
        float vstart = __shfl_up_sync(0xFFFFFFFFu, Bs, 1);
        if (lane == 0) vstart = 0.0f;
        float Aj = 1.0f;
        cj[0] = 0.52f * vstart;
        #pragma unroll
        for (int j = 1; j < CHUNK; ++j) {
            Aj *= 0.8f;
            cj[j] = 0.52f * fmaf(Aj, vstart, Bp[j - 1]);
        }
    }

    // ---- wait for copiers (zero wait on replays: flags persist) ------------
    {
        int ok;
        do {
            int f = g_flags[lane] & g_flags[lane + 32];
            ok = __all_sync(0xFFFFFFFFu, f);
        } while (!ok);
        __threadfence();
    }

    // table: global (L2-hot) -> SMEM, 8 float4 per thread
    {
        const float4* src = (const float4*)g_tab_dev;
        float4* dst = (float4*)tab;
        #pragma unroll
        for (int j = 0; j < NTAB / 2 / TPB; ++j)     // 256 float4 total
            dst[lane + j * TPB] = src[lane + j * TPB];
    }
    __syncwarp();   // table STS visible across lanes

    unsigned sbase = (unsigned)__cvta_generic_to_shared(tab);
    const unsigned OFFC = sbase - 0x58000000u;   // sbase - 8*0x4B000000 mod 2^32
    const float MAGIC = 8388608.0f;              // 2^23 (round-to-nearest)
    const float TMAX  = MAGIC + (float)(NTAB - 1);

    float klast = 0.0f;

    #pragma unroll 1
    for (int sw = 0; sw < NSWEEP; ++sw) {
        float knb = __shfl_up_sync(0xFFFFFFFFu, klast, 1);
        if (lane == 0) knb = 0.0f;

        float Al[CHUNK], Bl[CHUNK];
        float A = 1.0f, B = 0.0f;
        #pragma unroll
        for (int j = 0; j < CHUNK; ++j) {
            float kp = (j == 0) ? knb : k[j - 1];
            float s  = fmaf(kp, kp, su2[j]);
            float tt = fminf(fmaf(s, INV_DS, MAGIC), TMAX);
            unsigned addr = __float_as_uint(tt) * 8u + OFFC;
            float a_, b_;
            asm("ld.shared.v2.f32 {%0,%1},[%2];"
                : "=f"(a_), "=f"(b_) : "r"(addr));
            float g  = fmaf(b_, s, a_);
            float at = fmaf(0.28f, g, 0.8f);
            float bt = g * cj[j];
            B = fmaf(at, B, bt);
            A = at * A;
            Al[j] = A; Bl[j] = B;
        }

        float As = A, Bs = B;
        warp_scan_affine_Bout(As, Bs, lane);
        float kstart = __shfl_up_sync(0xFFFFFFFFu, Bs, 1);
        if (lane == 0) kstart = 0.0f;

        #pragma unroll
        for (int j = 0; j < CHUNK; ++j)
            k[j] = fmaf(Al[j], kstart, Bl[j]);
        klast = k[CHUNK - 1];
    }

    if (lane == 31) *out = tanhf(k[CHUNK - 1]);
}

// ---------------------------------------------------------------------------
// Host: Gauss-Legendre n=64 + table build (double precision, input-indep).
// ---------------------------------------------------------------------------
static void host_leggauss64(double* x, double* w) {
    const int n = GLN;
    const double PI = 3.14159265358979323846;
    for (int i = 0; i < n; ++i) {
        double xi = cos(PI * (i + 0.75) / (n + 0.5));
        double p0 = 1.0, p1 = 0.0, pp = 1.0;
        for (int it = 0; it < 100; ++it) {
            p0 = 1.0; p1 = 0.0;
            for (int j = 1; j <= n; ++j) {
                double p2 = p1; p1 = p0;
                p0 = ((2.0 * j - 1.0) * xi * p1 - (j - 1.0) * p2) / j;
            }
            pp = n * (xi * p0 - p1) / (xi * xi - 1.0);
            double dx = p0 / pp;
            xi -= dx;
            if (fabs(dx) < 1e-15) break;
        }
        p0 = 1.0; p1 = 0.0;
        for (int j = 1; j <= n; ++j) {
            double p2 = p1; p1 = p0;
            p0 = ((2.0 * j - 1.0) * xi * p1 - (j - 1.0) * p2) / j;
        }
        pp = n * (xi * p0 - p1) / (xi * xi - 1.0);
        x[i] = xi;
        w[i] = 2.0 / ((1.0 - xi * xi) * pp * pp);
    }
}

static double host_g(double s, const double* X, const double* EW) {
    double d = sqrt(s);
    double acc = 0.0;
    for (int q = 0; q < GLN; ++q) {
        double th = tanh(d * X[q]);
        acc += EW[q] * (1.0 - th * th);
    }
    return acc * 0.15915494309189535;   // 1/(2*pi)
}

static void host_build_table(TabParam* tp) {
    double x[GLN], wq[GLN], X[GLN], EW[GLN];
    host_leggauss64(x, wq);
    for (int q = 0; q < GLN; ++q) {
        X[q]  = x[q] * 5.0;
        EW[q] = wq[q] * 5.0 * exp(-X[q] * X[q] * 0.5);
    }
    const double ds = (double)S_MAX / (double)NTAB;
    for (int i = 0; i < NTAB; ++i) {
        double s  = i * ds;
        double h  = 0.5 * ds;
        double sl = (s - h > 0.0) ? (s - h) : 0.0;
        double sh = s + h;
        double g0 = host_g(s,  X, EW);
        double gm = host_g(sl, X, EW);
        double gp = host_g(sh, X, EW);
        double bb = (gp - gm) / (sh - sl);
        tp->e[i].x = (float)(g0 - bb * s);
        tp->e[i].y = (float)bb;
    }
}

// ---------------------------------------------------------------------------
extern "C" void kernel_launch(void* const* d_in, const int* in_sizes, int n_in,
                              void* d_out, int out_size) {
    (void)n_in; (void)out_size;
    const float* u = (const float*)d_in[0];
    float* out = (float*)d_out;
    int n = in_sizes[0];

    static TabParam tp;
    host_build_table(&tp);   // deterministic, host-side, input-independent

    run_kernel<<<NCOPY + 1, TPB>>>(tp, u, out, n);   // single graph node
}

// round 15
// speedup vs baseline: 1.3527x; 1.1691x over previous
#include <cuda_runtime.h>
#include <cuda_bf16.h>
#include <math.h>
#include <stdint.h>

// ----------------------------------------------------------------------------
// k' = k(0.8+0.28g) + 0.52 g v ; v' = 0.8 v + 0.2 u_t ; g = g(k^2+u^2).
// Out: tanh(k_final).   (64-pt GL quadrature folded into host-built table.)
//
// R15: MINIMAL kernel — grid=1, one warp, zero auxiliary machinery.
// - Contraction: only LAST W=128 steps from (0,0) matter (validated R12/R14).
// - Host-built linearized table g ~ a_i + b_i*s, NTAB=256 over [0,24], passed
//   by value as a 2KB kernel param. 2KB = 32 const lines: per-line serialized
//   const-miss cost is ~16-27cyc (R8 measurement), so direct const->SMEM
//   staging on the single SM is ~0.5-0.9k cyc — cheaper than the copier-block
//   + global + flag machinery it replaces (R13/R14 structure deleted).
// - Picard + affine warp scan, 5 sweeps (validated R7-R14).
// ----------------------------------------------------------------------------

#define GLN 64
#define NTAB 256
#define S_MAX 24.0f
#define INV_DS ((float)NTAB / S_MAX)
#define W 128
#define TPB 32
#define CHUNK 4           // W / TPB
#define NSWEEP 5

struct TabParam { float2 e[NTAB]; };   // 2048 bytes, by value

// ---------------------------------------------------------------------------
// Warp inclusive affine scan; last level computes B only (A unused after).
// ---------------------------------------------------------------------------
__device__ __forceinline__ void warp_scan_affine_Bout(float& A, float& B, int lane) {
    #pragma unroll
    for (int off = 1; off < 16; off <<= 1) {
        float Ag = __shfl_up_sync(0xFFFFFFFFu, A, off);
        float Bg = __shfl_up_sync(0xFFFFFFFFu, B, off);
        if (lane >= off) { B = fmaf(A, Bg, B); A *= Ag; }
    }
    float Bg = __shfl_up_sync(0xFFFFFFFFu, B, 16);
    if (lane >= 16) B = fmaf(A, Bg, B);
}

// ---------------------------------------------------------------------------
// The whole thing: one block, one warp.
// ---------------------------------------------------------------------------
__global__ void __launch_bounds__(TPB, 1)
run_kernel(TabParam tp, const float* __restrict__ u,
           float* __restrict__ out, int n) {
    __shared__ float2 tab[NTAB];   // 2 KB
    const int lane = threadIdx.x;

    // u window first (overlap DRAM/L2 latency with const staging)
    float su2[CHUNK], cj[CHUNK], k[CHUNK];
    const int base = n - W + lane * CHUNK;
    if (base >= 0) {                         // fast path (n >= W, aligned)
        float4 a = *(const float4*)(u + base);
        cj[0]=a.x; cj[1]=a.y; cj[2]=a.z; cj[3]=a.w;
    } else {
        #pragma unroll
        for (int j = 0; j < CHUNK; ++j) {
            int gi = base + j;
            cj[j] = (gi >= 0) ? u[gi] : 0.0f;   // zero-pad front (exact)
        }
    }
    #pragma unroll
    for (int j = 0; j < CHUNK; ++j) { su2[j] = cj[j] * cj[j]; k[j] = 0.0f; }

    // table: kernel-param (const bank) -> SMEM; 2KB = 32 lines, 2 float4/thread
    {
        const float4* src = (const float4*)tp.e;
        float4* dst = (float4*)tab;
        dst[lane]       = src[lane];
        dst[lane + 32]  = src[lane + 32];
    }

    // ---- v scan: v_t = 0.8 v_{t-1} + 0.2 u_t, v_0 = 0; cj = 0.52*v_{t-1} ---
    {
        float B = 0.0f;
        float Bp[CHUNK];
        #pragma unroll
        for (int j = 0; j < CHUNK; ++j) {
            B = fmaf(0.8f, B, 0.2f * cj[j]);
            Bp[j] = B;
        }
        float As = 0.40960000f;                // 0.8^4
        float Bs = B;
        warp_scan_affine_Bout(As, Bs, lane);
        float vstart = __shfl_up_sync(0xFFFFFFFFu, Bs, 1);
        if (lane == 0) vstart = 0.0f;
        float Aj = 1.0f;
        cj[0] = 0.52f * vstart;
        #pragma unroll
        for (int j = 1; j < CHUNK; ++j) {
            Aj *= 0.8f;
            cj[j] = 0.52f * fmaf(Aj, vstart, Bp[j - 1]);
        }
    }

    __syncwarp();   // table STS visible across lanes

    unsigned sbase = (unsigned)__cvta_generic_to_shared(tab);
    const unsigned OFFC = sbase - 0x58000000u;   // sbase - 8*0x4B000000 mod 2^32
    const float MAGIC = 8388608.0f;              // 2^23 (round-to-nearest)
    const float TMAX  = MAGIC + (float)(NTAB - 1);

    float klast = 0.0f;

    #pragma unroll 1
    for (int sw = 0; sw < NSWEEP; ++sw) {
        float knb = __shfl_up_sync(0xFFFFFFFFu, klast, 1);
        if (lane == 0) knb = 0.0f;

        float Al[CHUNK], Bl[CHUNK];
        float A = 1.0f, B = 0.0f;
        #pragma unroll
        for (int j = 0; j < CHUNK; ++j) {
            float kp = (j == 0) ? knb : k[j - 1];
            float s  = fmaf(kp, kp, su2[j]);
            float tt = fminf(fmaf(s, INV_DS, MAGIC), TMAX);
            unsigned addr = __float_as_uint(tt) * 8u + OFFC;
            float a_, b_;
            asm("ld.shared.v2.f32 {%0,%1},[%2];"
                : "=f"(a_), "=f"(b_) : "r"(addr));
            float g  = fmaf(b_, s, a_);
            float at = fmaf(0.28f, g, 0.8f);
            float bt = g * cj[j];
            B = fmaf(at, B, bt);
            A = at * A;
            Al[j] = A; Bl[j] = B;
        }

        float As = A, Bs = B;
        warp_scan_affine_Bout(As, Bs, lane);
        float kstart = __shfl_up_sync(0xFFFFFFFFu, Bs, 1);
        if (lane == 0) kstart = 0.0f;

        #pragma unroll
        for (int j = 0; j < CHUNK; ++j)
            k[j] = fmaf(Al[j], kstart, Bl[j]);
        klast = k[CHUNK - 1];
    }

    if (lane == 31) *out = tanhf(k[CHUNK - 1]);
}

// ---------------------------------------------------------------------------
// Host: Gauss-Legendre n=64 + table build (double precision, input-indep).
// ---------------------------------------------------------------------------
static void host_leggauss64(double* x, double* w) {
    const int n = GLN;
    const double PI = 3.14159265358979323846;
    for (int i = 0; i < n; ++i) {
        double xi = cos(PI * (i + 0.75) / (n + 0.5));
        double p0 = 1.0, p1 = 0.0, pp = 1.0;
        for (int it = 0; it < 100; ++it) {
            p0 = 1.0; p1 = 0.0;
            for (int j = 1; j <= n; ++j) {
                double p2 = p1; p1 = p0;
                p0 = ((2.0 * j - 1.0) * xi * p1 - (j - 1.0) * p2) / j;
            }
            pp = n * (xi * p0 - p1) / (xi * xi - 1.0);
            double dx = p0 / pp;
            xi -= dx;
            if (fabs(dx) < 1e-15) break;
        }
        p0 = 1.0; p1 = 0.0;
        for (int j = 1; j <= n; ++j) {
            double p2 = p1; p1 = p0;
            p0 = ((2.0 * j - 1.0) * xi * p1 - (j - 1.0) * p2) / j;
        }
        pp = n * (xi * p0 - p1) / (xi * xi - 1.0);
        x[i] = xi;
        w[i] = 2.0 / ((1.0 - xi * xi) * pp * pp);
    }
}

static double host_g(double s, const double* X, const double* EW) {
    double d = sqrt(s);
    double acc = 0.0;
    for (int q = 0; q < GLN; ++q) {
        double th = tanh(d * X[q]);
        acc += EW[q] * (1.0 - th * th);
    }
    return acc * 0.15915494309189535;   // 1/(2*pi)
}

static void host_build_table(TabParam* tp) {
    double x[GLN], wq[GLN], X[GLN], EW[GLN];
    host_leggauss64(x, wq);
    for (int q = 0; q < GLN; ++q) {
        X[q]  = x[q] * 5.0;
        EW[q] = wq[q] * 5.0 * exp(-X[q] * X[q] * 0.5);
    }
    const double ds = (double)S_MAX / (double)NTAB;
    for (int i = 0; i < NTAB; ++i) {
        double s  = i * ds;
        double h  = 0.5 * ds;
        double sl = (s - h > 0.0) ? (s - h) : 0.0;
        double sh = s + h;
        double g0 = host_g(s,  X, EW);
        double gm = host_g(sl, X, EW);
        double gp = host_g(sh, X, EW);
        double bb = (gp - gm) / (sh - sl);
        tp->e[i].x = (float)(g0 - bb * s);
        tp->e[i].y = (float)bb;
    }
}

// ---------------------------------------------------------------------------
extern "C" void kernel_launch(void* const* d_in, const int* in_sizes, int n_in,
                              void* d_out, int out_size) {
    (void)n_in; (void)out_size;
    const float* u = (const float*)d_in[0];
    float* out = (float*)d_out;
    int n = in_sizes[0];

    static TabParam tp;
    host_build_table(&tp);   // deterministic, host-side, input-independent

    run_kernel<<<1, TPB>>>(tp, u, out, n);   // single block, single warp
}